// round 8
// baseline (speedup 1.0000x reference)
#include <cuda_runtime.h>

// ShortConvolution: depthwise causal conv K=4 + SiLU.
// x: (B=4, T=4096, D=2048) fp32 ; weight: (D=2048, K=4) fp32
// y[b,t,d] = silu( sum_{k=0..3} w[d,k] * x[b, t+k-3, d] )   (x[t<0] = 0)
//
// R8: row-streaming layout. Each 256-thread block owns a 16-row time slab
//     and sweeps full 8KB rows sequentially (sequential ~155KB read stream +
//     128KB write stream per block -> DRAM row-buffer locality). 6-row smem
//     ring (48KB), cp.async depth-3, per-thread self-column dependencies ->
//     no __syncthreads in the mainloop.

#define B_ 4
#define T_ 4096
#define D_ 2048
#define DV_ (D_ / 4)     // 512 float4 per row (8KB)
#define RPB_ 16          // output rows per block
#define RING_ 6          // smem ring rows
#define BLOCK_ 256
#define NG_ (T_ / RPB_)  // 256 groups per batch

typedef unsigned long long u64;

__device__ __forceinline__ u64 pack2(float lo, float hi) {
    u64 r;
    asm("mov.b64 %0, {%1, %2};" : "=l"(r) : "f"(lo), "f"(hi));
    return r;
}
__device__ __forceinline__ void unpack2(u64 v, float& lo, float& hi) {
    asm("mov.b64 {%0, %1}, %2;" : "=f"(lo), "=f"(hi) : "l"(v));
}
__device__ __forceinline__ u64 fma2(u64 a, u64 b, u64 c) {
    u64 d;
    asm("fma.rn.f32x2 %0, %1, %2, %3;" : "=l"(d) : "l"(a), "l"(b), "l"(c));
    return d;
}
__device__ __forceinline__ u64 mul2(u64 a, u64 b) {
    u64 d;
    asm("mul.rn.f32x2 %0, %1, %2;" : "=l"(d) : "l"(a), "l"(b));
    return d;
}
__device__ __forceinline__ float tanh_fast(float v) {
    float r;
    asm("tanh.approx.f32 %0, %1;" : "=f"(r) : "f"(v));
    return r;
}
__device__ __forceinline__ void cp_async16(unsigned int smem_dst, const void* gsrc) {
    asm volatile("cp.async.cg.shared.global [%0], [%1], 16;"
                 :: "r"(smem_dst), "l"(gsrc) : "memory");
}
__device__ __forceinline__ void cp_commit() {
    asm volatile("cp.async.commit_group;" ::: "memory");
}

__global__ __launch_bounds__(BLOCK_, 4)
void shortconv_silu_kernel(const float4* __restrict__ x,
                           const float4* __restrict__ w,
                           float4* __restrict__ out) {
    // 6 full rows: 6 * 512 * 16B = 48KB
    __shared__ float4 ring[RING_][DV_];

    const int tid = threadIdx.x;
    const int bid = blockIdx.x;
    const int g   = bid % NG_;
    const int b   = bid / NG_;
    const int t0  = g * RPB_;            // first output row (time) of this slab

    // This thread owns columns c0 = tid and c1 = tid + 256 of every row.
    const int c0 = tid;
    const int c1 = tid + BLOCK_;

    // Weights for both columns (float4 = 4 channels each, 4 taps per channel).
    const float4 wa0 = __ldg(&w[4 * c0 + 0]);
    const float4 wb0 = __ldg(&w[4 * c0 + 1]);
    const float4 wc0 = __ldg(&w[4 * c0 + 2]);
    const float4 wd0 = __ldg(&w[4 * c0 + 3]);
    const float4 wa1 = __ldg(&w[4 * c1 + 0]);
    const float4 wb1 = __ldg(&w[4 * c1 + 1]);
    const float4 wc1 = __ldg(&w[4 * c1 + 2]);
    const float4 wd1 = __ldg(&w[4 * c1 + 3]);

    // Packed taps: lo = (.x,.y) channels, hi = (.z,.w) channels, per column.
    const u64 p0lo0 = pack2(wa0.x, wb0.x), p0lo1 = pack2(wa0.y, wb0.y);
    const u64 p0lo2 = pack2(wa0.z, wb0.z), p0lo3 = pack2(wa0.w, wb0.w);
    const u64 p0hi0 = pack2(wc0.x, wd0.x), p0hi1 = pack2(wc0.y, wd0.y);
    const u64 p0hi2 = pack2(wc0.z, wd0.z), p0hi3 = pack2(wc0.w, wd0.w);
    const u64 p1lo0 = pack2(wa1.x, wb1.x), p1lo1 = pack2(wa1.y, wb1.y);
    const u64 p1lo2 = pack2(wa1.z, wb1.z), p1lo3 = pack2(wa1.w, wb1.w);
    const u64 p1hi0 = pack2(wc1.x, wd1.x), p1hi1 = pack2(wc1.y, wd1.y);
    const u64 p1hi2 = pack2(wc1.z, wd1.z), p1hi3 = pack2(wc1.w, wd1.w);

    const u64 HALF2 = pack2(0.5f, 0.5f);

    const float4* __restrict__ xp = x + (size_t)b * T_ * DV_;
    float4* __restrict__ op = out + (size_t)b * T_ * DV_;

    // Prologue: rows i = 0..5  <->  t = t0-3 .. t0+2 (t0+2 <= T-1 always).
    // One commit group per row (empty group for zero-filled t<0 rows keeps
    // the wait_group accounting uniform).
#pragma unroll
    for (int i = 0; i < RING_; ++i) {
        const int t = t0 + i - 3;
        if (t >= 0) {
            cp_async16((unsigned int)__cvta_generic_to_shared(&ring[i][c0]),
                       &xp[(size_t)t * DV_ + c0]);
            cp_async16((unsigned int)__cvta_generic_to_shared(&ring[i][c1]),
                       &xp[(size_t)t * DV_ + c1]);
        } else {
            ring[i][c0] = make_float4(0.f, 0.f, 0.f, 0.f);
            ring[i][c1] = make_float4(0.f, 0.f, 0.f, 0.f);
        }
        cp_commit();
    }

#pragma unroll
    for (int r = 0; r < RPB_; ++r) {
        // Committed groups so far: 6 + r. Need rows i <= r+3 complete
        // (groups 1..r+4) -> at most 2 pending.
        asm volatile("cp.async.wait_group 2;" ::: "memory");

        const int s0 = (r + 0) % RING_;
        const int s1 = (r + 1) % RING_;
        const int s2 = (r + 2) % RING_;
        const int s3 = (r + 3) % RING_;
        const int t  = t0 + r;

        // ---- column c0 ----
        {
            const float4 x0 = ring[s0][c0], x1 = ring[s1][c0];
            const float4 x2 = ring[s2][c0], x3 = ring[s3][c0];
            u64 ylo = mul2(p0lo3, pack2(x3.x, x3.y));
            ylo = fma2(p0lo2, pack2(x2.x, x2.y), ylo);
            ylo = fma2(p0lo1, pack2(x1.x, x1.y), ylo);
            ylo = fma2(p0lo0, pack2(x0.x, x0.y), ylo);
            u64 yhi = mul2(p0hi3, pack2(x3.z, x3.w));
            yhi = fma2(p0hi2, pack2(x2.z, x2.w), yhi);
            yhi = fma2(p0hi1, pack2(x1.z, x1.w), yhi);
            yhi = fma2(p0hi0, pack2(x0.z, x0.w), yhi);

            const u64 hlo = mul2(ylo, HALF2);
            const u64 hhi = mul2(yhi, HALF2);
            float h0, h1, h2, h3;
            unpack2(hlo, h0, h1);
            unpack2(hhi, h2, h3);
            const u64 slo = fma2(pack2(tanh_fast(h0), tanh_fast(h1)), HALF2, HALF2);
            const u64 shi = fma2(pack2(tanh_fast(h2), tanh_fast(h3)), HALF2, HALF2);
            const u64 olo = mul2(ylo, slo);
            const u64 ohi = mul2(yhi, shi);
            float4 o;
            unpack2(olo, o.x, o.y);
            unpack2(ohi, o.z, o.w);
            op[(size_t)t * DV_ + c0] = o;
        }
        // ---- column c1 ----
        {
            const float4 x0 = ring[s0][c1], x1 = ring[s1][c1];
            const float4 x2 = ring[s2][c1], x3 = ring[s3][c1];
            u64 ylo = mul2(p1lo3, pack2(x3.x, x3.y));
            ylo = fma2(p1lo2, pack2(x2.x, x2.y), ylo);
            ylo = fma2(p1lo1, pack2(x1.x, x1.y), ylo);
            ylo = fma2(p1lo0, pack2(x0.x, x0.y), ylo);
            u64 yhi = mul2(p1hi3, pack2(x3.z, x3.w));
            yhi = fma2(p1hi2, pack2(x2.z, x2.w), yhi);
            yhi = fma2(p1hi1, pack2(x1.z, x1.w), yhi);
            yhi = fma2(p1hi0, pack2(x0.z, x0.w), yhi);

            const u64 hlo = mul2(ylo, HALF2);
            const u64 hhi = mul2(yhi, HALF2);
            float h0, h1, h2, h3;
            unpack2(hlo, h0, h1);
            unpack2(hhi, h2, h3);
            const u64 slo = fma2(pack2(tanh_fast(h0), tanh_fast(h1)), HALF2, HALF2);
            const u64 shi = fma2(pack2(tanh_fast(h2), tanh_fast(h3)), HALF2, HALF2);
            const u64 olo = mul2(ylo, slo);
            const u64 ohi = mul2(yhi, shi);
            float4 o;
            unpack2(olo, o.x, o.y);
            unpack2(ohi, o.z, o.w);
            op[(size_t)t * DV_ + c1] = o;
        }

        // Post row i = r+6 (t = t0+r+3) into the slot just freed (s0).
        // Last needed input row is t0+RPB-1 -> post only while r <= RPB-4.
        if (r <= RPB_ - 4) {
            const int tn = t0 + r + 3;
            cp_async16((unsigned int)__cvta_generic_to_shared(&ring[s0][c0]),
                       &xp[(size_t)tn * DV_ + c0]);
            cp_async16((unsigned int)__cvta_generic_to_shared(&ring[s0][c1]),
                       &xp[(size_t)tn * DV_ + c1]);
        }
        cp_commit();  // always commit -> uniform group accounting
    }
}

extern "C" void kernel_launch(void* const* d_in, const int* in_sizes, int n_in,
                              void* d_out, int out_size) {
    const float4* x = (const float4*)d_in[0];
    const float4* w = (const float4*)d_in[1];
    float4* out = (float4*)d_out;

    const int grid = B_ * NG_;   // 4 * 256 = 1024 blocks
    shortconv_silu_kernel<<<grid, BLOCK_>>>(x, w, out);
}

// round 9
// speedup vs baseline: 1.0876x; 1.0876x over previous
#include <cuda_runtime.h>

// ShortConvolution: depthwise causal conv K=4 + SiLU.
// x: (B=4, T=4096, D=2048) fp32 ; weight: (D=2048, K=4) fp32
// y[b,t,d] = silu( sum_{k=0..3} w[d,k] * x[b, t+k-3, d] )   (x[t<0] = 0)
//
// R9 = R2 (empirical best, 45.088us) resubmitted for confirmation.
// Structure: one thread owns 4 channels x 8 timesteps; 11 front-batched
// LDG.128 (halo shared via L2 with neighbor CTAs -> ~1.0x DRAM reads);
// packed f32x2 conv math; single-MUFU SiLU via tanh.approx.
// 8 rounds of structural sweeps (occupancy 31-53%, cp.async depth 0-3,
// TPT 4/8, row-streaming) all pin DRAM at 71-75% -> this is the mixed
// read/write HBM efficiency ceiling; R2 is the simplest member of the
// top cluster and the bench-best.

#define B_ 4
#define T_ 4096
#define D_ 2048
#define DV_ (D_ / 4)        // 512 float4 lanes across channels
#define TPT_ 8              // time steps per thread
#define NCHUNK_ (T_ / TPT_) // 512

typedef unsigned long long u64;

__device__ __forceinline__ u64 pack2(float lo, float hi) {
    u64 r;
    asm("mov.b64 %0, {%1, %2};" : "=l"(r) : "f"(lo), "f"(hi));
    return r;
}
__device__ __forceinline__ void unpack2(u64 v, float& lo, float& hi) {
    asm("mov.b64 {%0, %1}, %2;" : "=f"(lo), "=f"(hi) : "l"(v));
}
__device__ __forceinline__ u64 fma2(u64 a, u64 b, u64 c) {
    u64 d;
    asm("fma.rn.f32x2 %0, %1, %2, %3;" : "=l"(d) : "l"(a), "l"(b), "l"(c));
    return d;
}
__device__ __forceinline__ u64 mul2(u64 a, u64 b) {
    u64 d;
    asm("mul.rn.f32x2 %0, %1, %2;" : "=l"(d) : "l"(a), "l"(b));
    return d;
}
__device__ __forceinline__ float tanh_fast(float v) {
    float r;
    asm("tanh.approx.f32 %0, %1;" : "=f"(r) : "f"(v));
    return r;
}

__global__ __launch_bounds__(256, 4)
void shortconv_silu_kernel(const float4* __restrict__ x,
                           const float4* __restrict__ w,
                           float4* __restrict__ out) {
    const int gid = blockIdx.x * blockDim.x + threadIdx.x;
    const int dv  = gid % DV_;              // float4 lane along channels
    const int row = gid / DV_;              // (b, t-chunk)
    const int t0  = (row % NCHUNK_) * TPT_;
    const int b   = row / NCHUNK_;

    // weight layout (D, K): float4 w[c] = the 4 taps of channel c.
    // This thread owns channels 4*dv .. 4*dv+3.
    const float4 wa = __ldg(&w[4 * dv + 0]);  // taps for .x channel
    const float4 wb = __ldg(&w[4 * dv + 1]);  // taps for .y channel
    const float4 wc = __ldg(&w[4 * dv + 2]);  // taps for .z channel
    const float4 wd = __ldg(&w[4 * dv + 3]);  // taps for .w channel

    // Packed taps: lo = channels (.x,.y), hi = channels (.z,.w)
    const u64 wlo0 = pack2(wa.x, wb.x), wlo1 = pack2(wa.y, wb.y);
    const u64 wlo2 = pack2(wa.z, wb.z), wlo3 = pack2(wa.w, wb.w);
    const u64 whi0 = pack2(wc.x, wd.x), whi1 = pack2(wc.y, wd.y);
    const u64 whi2 = pack2(wc.z, wd.z), whi3 = pack2(wc.w, wd.w);

    const u64 HALF2 = pack2(0.5f, 0.5f);

    const size_t base = (size_t)b * T_ * DV_ + dv;
    const float4* __restrict__ xp = x + base;
    float4* __restrict__ op = out + base;

    // Load TPT+3 time samples (halo of 3 on the left; zero for t<0).
    u64 xlo[TPT_ + 3], xhi[TPT_ + 3];
#pragma unroll
    for (int i = 0; i < TPT_ + 3; ++i) {
        const int t = t0 + i - 3;
        float4 v = make_float4(0.f, 0.f, 0.f, 0.f);
        if (t >= 0) v = __ldg(&xp[(size_t)t * DV_]);
        xlo[i] = pack2(v.x, v.y);
        xhi[i] = pack2(v.z, v.w);
    }

#pragma unroll
    for (int j = 0; j < TPT_; ++j) {
        // y = w0*x[j] + w1*x[j+1] + w2*x[j+2] + w3*x[j+3]
        u64 alo = mul2(wlo3, xlo[j + 3]);
        alo = fma2(wlo2, xlo[j + 2], alo);
        alo = fma2(wlo1, xlo[j + 1], alo);
        alo = fma2(wlo0, xlo[j + 0], alo);

        u64 ahi = mul2(whi3, xhi[j + 3]);
        ahi = fma2(whi2, xhi[j + 2], ahi);
        ahi = fma2(whi1, xhi[j + 1], ahi);
        ahi = fma2(whi0, xhi[j + 0], ahi);

        // SiLU: y * (0.5*tanh(0.5*y) + 0.5)   (single MUFU per element)
        u64 hlo = mul2(alo, HALF2);
        u64 hhi = mul2(ahi, HALF2);
        float h0, h1, h2, h3;
        unpack2(hlo, h0, h1);
        unpack2(hhi, h2, h3);
        const u64 tlo = pack2(tanh_fast(h0), tanh_fast(h1));
        const u64 thi = pack2(tanh_fast(h2), tanh_fast(h3));
        const u64 slo = fma2(tlo, HALF2, HALF2);
        const u64 shi = fma2(thi, HALF2, HALF2);
        const u64 ylo = mul2(alo, slo);
        const u64 yhi = mul2(ahi, shi);

        float4 o;
        unpack2(ylo, o.x, o.y);
        unpack2(yhi, o.z, o.w);
        op[(size_t)(t0 + j) * DV_] = o;
    }
}

extern "C" void kernel_launch(void* const* d_in, const int* in_sizes, int n_in,
                              void* d_out, int out_size) {
    const float4* x = (const float4*)d_in[0];
    const float4* w = (const float4*)d_in[1];
    float4* out = (float4*)d_out;

    const int total_threads = B_ * NCHUNK_ * DV_;   // 4 * 512 * 512 = 1,048,576
    const int block = 256;
    const int grid = total_threads / block;          // 4096

    shortconv_silu_kernel<<<grid, block>>>(x, w, out);
}

// round 10
// speedup vs baseline: 1.1007x; 1.0121x over previous
#include <cuda_runtime.h>

// ShortConvolution: depthwise causal conv K=4 + SiLU.
// x: (B=4, T=4096, D=2048) fp32 ; weight: (D=2048, K=4) fp32
// y[b,t,d] = silu( sum_{k=0..3} w[d,k] * x[b, t+k-3, d] )   (x[t<0] = 0)
//
// R10 = R2 (bench-best structure, confirmed reproducible in R9) + __stcs
// evict-first output stores ONLY. Isolates the store-policy variable:
// theory is ~45MB of dirty L2 at kernel end drains into the next graph
// replay (the ~8us bench-vs-ncu gap); streaming writes start writeback
// earlier and keep L2 for halo read reuse.

#define B_ 4
#define T_ 4096
#define D_ 2048
#define DV_ (D_ / 4)        // 512 float4 lanes across channels
#define TPT_ 8              // time steps per thread
#define NCHUNK_ (T_ / TPT_) // 512

typedef unsigned long long u64;

__device__ __forceinline__ u64 pack2(float lo, float hi) {
    u64 r;
    asm("mov.b64 %0, {%1, %2};" : "=l"(r) : "f"(lo), "f"(hi));
    return r;
}
__device__ __forceinline__ void unpack2(u64 v, float& lo, float& hi) {
    asm("mov.b64 {%0, %1}, %2;" : "=f"(lo), "=f"(hi) : "l"(v));
}
__device__ __forceinline__ u64 fma2(u64 a, u64 b, u64 c) {
    u64 d;
    asm("fma.rn.f32x2 %0, %1, %2, %3;" : "=l"(d) : "l"(a), "l"(b), "l"(c));
    return d;
}
__device__ __forceinline__ u64 mul2(u64 a, u64 b) {
    u64 d;
    asm("mul.rn.f32x2 %0, %1, %2;" : "=l"(d) : "l"(a), "l"(b));
    return d;
}
__device__ __forceinline__ float tanh_fast(float v) {
    float r;
    asm("tanh.approx.f32 %0, %1;" : "=f"(r) : "f"(v));
    return r;
}

__global__ __launch_bounds__(256, 4)
void shortconv_silu_kernel(const float4* __restrict__ x,
                           const float4* __restrict__ w,
                           float4* __restrict__ out) {
    const int gid = blockIdx.x * blockDim.x + threadIdx.x;
    const int dv  = gid % DV_;              // float4 lane along channels
    const int row = gid / DV_;              // (b, t-chunk)
    const int t0  = (row % NCHUNK_) * TPT_;
    const int b   = row / NCHUNK_;

    // weight layout (D, K): float4 w[c] = the 4 taps of channel c.
    // This thread owns channels 4*dv .. 4*dv+3.
    const float4 wa = __ldg(&w[4 * dv + 0]);  // taps for .x channel
    const float4 wb = __ldg(&w[4 * dv + 1]);  // taps for .y channel
    const float4 wc = __ldg(&w[4 * dv + 2]);  // taps for .z channel
    const float4 wd = __ldg(&w[4 * dv + 3]);  // taps for .w channel

    // Packed taps: lo = channels (.x,.y), hi = channels (.z,.w)
    const u64 wlo0 = pack2(wa.x, wb.x), wlo1 = pack2(wa.y, wb.y);
    const u64 wlo2 = pack2(wa.z, wb.z), wlo3 = pack2(wa.w, wb.w);
    const u64 whi0 = pack2(wc.x, wd.x), whi1 = pack2(wc.y, wd.y);
    const u64 whi2 = pack2(wc.z, wd.z), whi3 = pack2(wc.w, wd.w);

    const u64 HALF2 = pack2(0.5f, 0.5f);

    const size_t base = (size_t)b * T_ * DV_ + dv;
    const float4* __restrict__ xp = x + base;
    float4* __restrict__ op = out + base;

    // Load TPT+3 time samples (halo of 3 on the left; zero for t<0).
    u64 xlo[TPT_ + 3], xhi[TPT_ + 3];
#pragma unroll
    for (int i = 0; i < TPT_ + 3; ++i) {
        const int t = t0 + i - 3;
        float4 v = make_float4(0.f, 0.f, 0.f, 0.f);
        if (t >= 0) v = __ldg(&xp[(size_t)t * DV_]);
        xlo[i] = pack2(v.x, v.y);
        xhi[i] = pack2(v.z, v.w);
    }

#pragma unroll
    for (int j = 0; j < TPT_; ++j) {
        // y = w0*x[j] + w1*x[j+1] + w2*x[j+2] + w3*x[j+3]
        u64 alo = mul2(wlo3, xlo[j + 3]);
        alo = fma2(wlo2, xlo[j + 2], alo);
        alo = fma2(wlo1, xlo[j + 1], alo);
        alo = fma2(wlo0, xlo[j + 0], alo);

        u64 ahi = mul2(whi3, xhi[j + 3]);
        ahi = fma2(whi2, xhi[j + 2], ahi);
        ahi = fma2(whi1, xhi[j + 1], ahi);
        ahi = fma2(whi0, xhi[j + 0], ahi);

        // SiLU: y * (0.5*tanh(0.5*y) + 0.5)   (single MUFU per element)
        u64 hlo = mul2(alo, HALF2);
        u64 hhi = mul2(ahi, HALF2);
        float h0, h1, h2, h3;
        unpack2(hlo, h0, h1);
        unpack2(hhi, h2, h3);
        const u64 tlo = pack2(tanh_fast(h0), tanh_fast(h1));
        const u64 thi = pack2(tanh_fast(h2), tanh_fast(h3));
        const u64 slo = fma2(tlo, HALF2, HALF2);
        const u64 shi = fma2(thi, HALF2, HALF2);
        const u64 ylo = mul2(alo, slo);
        const u64 yhi = mul2(ahi, shi);

        float4 o;
        unpack2(ylo, o.x, o.y);
        unpack2(yhi, o.z, o.w);
        // Evict-first streaming store: output is write-once, never re-read.
        __stcs(&op[(size_t)(t0 + j) * DV_], o);
    }
}

extern "C" void kernel_launch(void* const* d_in, const int* in_sizes, int n_in,
                              void* d_out, int out_size) {
    const float4* x = (const float4*)d_in[0];
    const float4* w = (const float4*)d_in[1];
    float4* out = (float4*)d_out;

    const int total_threads = B_ * NCHUNK_ * DV_;   // 4 * 512 * 512 = 1,048,576
    const int block = 256;
    const int grid = total_threads / block;          // 4096

    shortconv_silu_kernel<<<grid, block>>>(x, w, out);
}